// round 1
// baseline (speedup 1.0000x reference)
#include <cuda_runtime.h>
#include <math.h>

#define Bv 4
#define Tv 2048
#define Cv 1024
#define Hv 16
#define Dv 64
#define Mv (Bv*Tv)          // 8192 rows
#define PADR 68             // padded row stride (floats) for flash smem tiles

// Scratch (device globals: allocation-free per harness rules)
__device__ float g_q[Mv*Cv];
__device__ float g_k[Mv*Cv];
__device__ float g_v[Mv*Cv];
__device__ float g_att[Mv*Cv];

// ---------------------------------------------------------------------------
// C[M,N] = A[M,K] * B[N,K]^T   (both row-major, K contiguous: C=A·B^T)
// 128x128 block tile, BK=8, 256 threads, 8x8 per-thread micro-tile.
// ---------------------------------------------------------------------------
__global__ __launch_bounds__(256, 2)
void sgemm_nt(const float* __restrict__ A, const float* __restrict__ B,
              float* __restrict__ Cm, int M, int N, int K)
{
    __shared__ float As[8][132];   // [k][m], padded
    __shared__ float Bs[8][132];   // [k][n], padded

    const int tid = threadIdx.x;
    const int tx = tid & 15;
    const int ty = tid >> 4;
    const int m0 = blockIdx.y << 7;
    const int n0 = blockIdx.x << 7;

    // loader mapping: 2 threads per row, float4 each -> 128 rows x 8 k
    const int lr = tid >> 1;
    const int lc = (tid & 1) << 2;
    const float* Ap = A + (size_t)(m0 + lr) * K + lc;
    const float* Bp = B + (size_t)(n0 + lr) * K + lc;

    float acc[8][8];
    #pragma unroll
    for (int i = 0; i < 8; i++)
        #pragma unroll
        for (int j = 0; j < 8; j++) acc[i][j] = 0.f;

    for (int k0 = 0; k0 < K; k0 += 8) {
        float4 av = *(const float4*)(Ap + k0);
        float4 bv = *(const float4*)(Bp + k0);
        __syncthreads();
        As[lc+0][lr] = av.x; As[lc+1][lr] = av.y;
        As[lc+2][lr] = av.z; As[lc+3][lr] = av.w;
        Bs[lc+0][lr] = bv.x; Bs[lc+1][lr] = bv.y;
        Bs[lc+2][lr] = bv.z; Bs[lc+3][lr] = bv.w;
        __syncthreads();

        #pragma unroll
        for (int kk = 0; kk < 8; kk++) {
            float a[8], b[8];
            *(float4*)(a)     = *(const float4*)&As[kk][ty*8];
            *(float4*)(a + 4) = *(const float4*)&As[kk][ty*8 + 4];
            *(float4*)(b)     = *(const float4*)&Bs[kk][tx*8];
            *(float4*)(b + 4) = *(const float4*)&Bs[kk][tx*8 + 4];
            #pragma unroll
            for (int i = 0; i < 8; i++)
                #pragma unroll
                for (int j = 0; j < 8; j++)
                    acc[i][j] = fmaf(a[i], b[j], acc[i][j]);
        }
    }

    #pragma unroll
    for (int i = 0; i < 8; i++) {
        float* crow = Cm + (size_t)(m0 + ty*8 + i) * N + n0 + tx*8;
        *(float4*)(crow)     = make_float4(acc[i][0], acc[i][1], acc[i][2], acc[i][3]);
        *(float4*)(crow + 4) = make_float4(acc[i][4], acc[i][5], acc[i][6], acc[i][7]);
    }
}

// ---------------------------------------------------------------------------
// Causal flash attention. One block per (64 query rows, b*H+h).
// 256 threads as 16x16; each thread owns a 4x4 score / output micro-tile.
// smem: Qs[64][68] (i,d), Vs[64][68] (j,d), KtP[64][68] (Kt as [d][j], reused
// as P [i][j] after the score phase).
// ---------------------------------------------------------------------------
__global__ __launch_bounds__(256)
void flash_causal(const float* __restrict__ Qg, const float* __restrict__ Kg,
                  const float* __restrict__ Vg, float* __restrict__ Og)
{
    extern __shared__ float sm[];
    float* Qs  = sm;                 // [64][PADR]
    float* Vs  = sm + 64 * PADR;     // [64][PADR]
    float* KtP = sm + 2 * 64 * PADR; // [64][PADR]

    const int tid = threadIdx.x;
    const int tx = tid & 15;
    const int ty = tid >> 4;
    const int qt = blockIdx.x;
    const int bh = blockIdx.y;
    const int b  = bh >> 4;          // / Hv
    const int h  = bh & 15;          // % Hv
    const int q0 = qt * 64;
    const size_t base = ((size_t)b * Tv) * Cv + (size_t)h * Dv;

    // load Q tile (coalesced)
    #pragma unroll
    for (int it = 0; it < 16; ++it) {
        int e = tid + it * 256;      // 0..4095
        int d = e & 63, r = e >> 6;
        Qs[r * PADR + d] = Qg[base + (size_t)(q0 + r) * Cv + d];
    }

    float m[4], l[4], acc[4][4];
    #pragma unroll
    for (int i = 0; i < 4; i++) {
        m[i] = -3.0e38f; l[i] = 0.f;
        #pragma unroll
        for (int j = 0; j < 4; j++) acc[i][j] = 0.f;
    }
    __syncthreads();

    const float SC = 0.125f;   // 1/sqrt(64)

    for (int kt = 0; kt <= qt; ++kt) {
        const int k0 = kt * 64;

        // load K (transposed to [d][j]) and V (natural [j][d])
        #pragma unroll
        for (int it = 0; it < 16; ++it) {
            int e = tid + it * 256;
            int d = e & 63, r = e >> 6;
            size_t g = base + (size_t)(k0 + r) * Cv + d;
            KtP[d * PADR + r] = Kg[g];
            Vs[r * PADR + d]  = Vg[g];
        }
        __syncthreads();

        // S = Q K^T  (4x4 per thread)
        float s[4][4];
        #pragma unroll
        for (int i = 0; i < 4; i++)
            #pragma unroll
            for (int j = 0; j < 4; j++) s[i][j] = 0.f;

        #pragma unroll 8
        for (int d = 0; d < 64; ++d) {
            float4 kv = *(const float4*)&KtP[d * PADR + tx * 4];
            float bb[4] = {kv.x, kv.y, kv.z, kv.w};
            float aa[4];
            #pragma unroll
            for (int i = 0; i < 4; i++) aa[i] = Qs[(ty*4 + i) * PADR + d];
            #pragma unroll
            for (int i = 0; i < 4; i++)
                #pragma unroll
                for (int j = 0; j < 4; j++)
                    s[i][j] = fmaf(aa[i], bb[j], s[i][j]);
        }

        // scale + causal mask (only diagonal tile needs masking)
        const bool diag = (kt == qt);
        #pragma unroll
        for (int i = 0; i < 4; i++) {
            const int qi = q0 + ty*4 + i;
            #pragma unroll
            for (int j = 0; j < 4; j++) {
                float sv = s[i][j] * SC;
                if (diag && (k0 + tx*4 + j > qi)) sv = -1.0e30f;
                s[i][j] = sv;
            }
        }

        // online softmax update (reduce over the 16-lane tx group)
        #pragma unroll
        for (int i = 0; i < 4; i++) {
            float mx = fmaxf(fmaxf(s[i][0], s[i][1]), fmaxf(s[i][2], s[i][3]));
            #pragma unroll
            for (int off = 1; off < 16; off <<= 1)
                mx = fmaxf(mx, __shfl_xor_sync(0xffffffffu, mx, off));
            float nm = fmaxf(m[i], mx);
            float rs = 0.f;
            #pragma unroll
            for (int j = 0; j < 4; j++) {
                float p = __expf(s[i][j] - nm);
                s[i][j] = p;
                rs += p;
            }
            #pragma unroll
            for (int off = 1; off < 16; off <<= 1)
                rs += __shfl_xor_sync(0xffffffffu, rs, off);
            float al = __expf(m[i] - nm);
            l[i] = l[i] * al + rs;
            m[i] = nm;
            #pragma unroll
            for (int j = 0; j < 4; j++) acc[i][j] *= al;
        }

        __syncthreads();   // done reading KtP as K^T
        // store P into KtP as [i][j]
        #pragma unroll
        for (int i = 0; i < 4; i++)
            *(float4*)&KtP[(ty*4 + i) * PADR + tx*4] =
                make_float4(s[i][0], s[i][1], s[i][2], s[i][3]);
        __syncthreads();

        // O += P V
        #pragma unroll 8
        for (int j = 0; j < 64; ++j) {
            float4 vv = *(const float4*)&Vs[j * PADR + tx * 4];
            float pp[4];
            #pragma unroll
            for (int i = 0; i < 4; i++) pp[i] = KtP[(ty*4 + i) * PADR + j];
            #pragma unroll
            for (int i = 0; i < 4; i++) {
                acc[i][0] = fmaf(pp[i], vv.x, acc[i][0]);
                acc[i][1] = fmaf(pp[i], vv.y, acc[i][1]);
                acc[i][2] = fmaf(pp[i], vv.z, acc[i][2]);
                acc[i][3] = fmaf(pp[i], vv.w, acc[i][3]);
            }
        }
        __syncthreads();   // before overwriting Vs/KtP next tile
    }

    // normalize and write out [b, t, h*64 + d]
    #pragma unroll
    for (int i = 0; i < 4; i++) {
        float inv = 1.0f / l[i];
        int r = q0 + ty*4 + i;
        *(float4*)&Og[base + (size_t)r * Cv + tx*4] =
            make_float4(acc[i][0]*inv, acc[i][1]*inv, acc[i][2]*inv, acc[i][3]*inv);
    }
}

// ---------------------------------------------------------------------------
extern "C" void kernel_launch(void* const* d_in, const int* in_sizes, int n_in,
                              void* d_out, int out_size)
{
    const float* x  = (const float*)d_in[0];
    const float* wq = (const float*)d_in[1];
    const float* wk = (const float*)d_in[2];
    const float* wv = (const float*)d_in[3];
    const float* wo = (const float*)d_in[4];
    float* out = (float*)d_out;

    float *qp, *kp, *vp, *ap;
    cudaGetSymbolAddress((void**)&qp, g_q);
    cudaGetSymbolAddress((void**)&kp, g_k);
    cudaGetSymbolAddress((void**)&vp, g_v);
    cudaGetSymbolAddress((void**)&ap, g_att);

    dim3 gg(Cv/128, Mv/128);   // (8, 64)
    sgemm_nt<<<gg, 256>>>(x, wq, qp, Mv, Cv, Cv);
    sgemm_nt<<<gg, 256>>>(x, wk, kp, Mv, Cv, Cv);
    sgemm_nt<<<gg, 256>>>(x, wv, vp, Mv, Cv, Cv);

    int smem = 3 * 64 * PADR * (int)sizeof(float);   // 52224 B > 48K -> opt in
    cudaFuncSetAttribute(flash_causal,
                         cudaFuncAttributeMaxDynamicSharedMemorySize, smem);
    flash_causal<<<dim3(Tv/64, Bv*Hv), 256, smem>>>(qp, kp, vp, ap);

    sgemm_nt<<<gg, 256>>>(ap, wo, out, Mv, Cv, Cv);
}

// round 3
// speedup vs baseline: 1.8069x; 1.8069x over previous
#include <cuda_runtime.h>
#include <cstdint>
#include <math.h>

#define Bv 4
#define Tv 2048
#define Cv 1024
#define Hv 16
#define Dv 64
#define Mv (Bv*Tv)          // 8192 rows
#define PADR 68             // padded row stride (floats) for flash smem tiles

// ---------------- scratch (device globals; no allocations allowed) ----------
__device__ float g_q[Mv*Cv];
__device__ float g_k[Mv*Cv];
__device__ float g_v[Mv*Cv];
__device__ float g_att[Mv*Cv];
__device__ float g_xr[Mv*Cv];        // tf32-rounded x
__device__ float g_wr[4*Cv*Cv];      // tf32-rounded wq,wk,wv,wo

__device__ __forceinline__ uint32_t smem_u32(const void* p) {
    uint32_t a;
    asm("{ .reg .u64 t; cvta.to.shared.u64 t, %1; cvt.u32.u64 %0, t; }"
        : "=r"(a) : "l"(p));
    return a;
}

// ---------------------------------------------------------------------------
// elementwise round-to-tf32 (RN)
// ---------------------------------------------------------------------------
__global__ void round_tf32_k(const float4* __restrict__ in, float4* __restrict__ out, int n4)
{
    int i = blockIdx.x * blockDim.x + threadIdx.x;
    if (i >= n4) return;
    float4 v = in[i];
    uint32_t a, b, c, d;
    asm("cvt.rn.tf32.f32 %0, %1;" : "=r"(a) : "f"(v.x));
    asm("cvt.rn.tf32.f32 %0, %1;" : "=r"(b) : "f"(v.y));
    asm("cvt.rn.tf32.f32 %0, %1;" : "=r"(c) : "f"(v.z));
    asm("cvt.rn.tf32.f32 %0, %1;" : "=r"(d) : "f"(v.w));
    out[i] = make_float4(__uint_as_float(a), __uint_as_float(b),
                         __uint_as_float(c), __uint_as_float(d));
}

// ---------------------------------------------------------------------------
// tf32 mma.sync GEMM:  C[M,N] = A[M,K] · B[N,K]^T   (A,B row-major, K contig)
// CTA 128x128, BK=32, 256 thr (8 warps as 2x4, warp tile 64x32),
// cp.async double buffer, ldmatrix.b16 fragment loads (f32 pairs).
// ---------------------------------------------------------------------------
#define GBK   32
#define LDS_  36                         // padded row stride (floats)
#define ABUF  (128*LDS_*4)               // 18432 B
#define STGB  (2*ABUF)                   // A+B per stage = 36864 B
#define NITER (Cv/GBK)                   // 32

__device__ __forceinline__ void cp16(uint32_t saddr, const void* gaddr) {
    asm volatile("cp.async.cg.shared.global [%0], [%1], 16;"
                 :: "r"(saddr), "l"(gaddr));
}

__device__ __forceinline__ void mma_tf32(float* d, const uint32_t* a, const uint32_t* b) {
    asm volatile("mma.sync.aligned.m16n8k8.row.col.f32.tf32.tf32.f32 "
                 "{%0,%1,%2,%3}, {%4,%5,%6,%7}, {%8,%9}, {%0,%1,%2,%3};"
                 : "+f"(d[0]), "+f"(d[1]), "+f"(d[2]), "+f"(d[3])
                 : "r"(a[0]), "r"(a[1]), "r"(a[2]), "r"(a[3]), "r"(b[0]), "r"(b[1]));
}

__global__ __launch_bounds__(256)
void gemm_tf32(const float* __restrict__ A, const float* __restrict__ B,
               float* __restrict__ C)
{
    extern __shared__ __align__(128) char smem[];
    const uint32_t sb = smem_u32(smem);
    const int tid  = threadIdx.x;
    const int wid  = tid >> 5;
    const int lane = tid & 31;
    const int m0 = blockIdx.y * 128, n0 = blockIdx.x * 128;
    const int wm = (wid >> 2) * 64;        // warp row offset in tile
    const int wn = (wid & 3) * 32;         // warp col offset in tile

    // loader mapping: 1024 x 16B chunks per (A or B) tile, 4 per thread
    // idx = tid + i*256 ; r = idx>>3 ; c4 = idx&7
    const int lr = tid >> 3;               // base row (adds 32 per i)
    const int lc = (tid & 7) * 4;          // f32 col

    float acc[4][4][4];
    #pragma unroll
    for (int i = 0; i < 4; i++)
        #pragma unroll
        for (int j = 0; j < 4; j++)
            #pragma unroll
            for (int k = 0; k < 4; k++) acc[i][j][k] = 0.f;

    // ---- prologue: stage 0 loads
    {
        const uint32_t sA = sb, sB = sb + ABUF;
        #pragma unroll
        for (int i = 0; i < 4; i++) {
            int r = lr + i * 32;
            cp16(sA + (r * LDS_ + lc) * 4, A + (size_t)(m0 + r) * Cv + lc);
            cp16(sB + (r * LDS_ + lc) * 4, B + (size_t)(n0 + r) * Cv + lc);
        }
        asm volatile("cp.async.commit_group;");
    }

    for (int it = 0; it < NITER; ++it) {
        if (it + 1 < NITER) {
            const int k0 = (it + 1) * GBK;
            const uint32_t base = sb + ((it + 1) & 1) * STGB;
            const uint32_t sA = base, sB = base + ABUF;
            #pragma unroll
            for (int i = 0; i < 4; i++) {
                int r = lr + i * 32;
                cp16(sA + (r * LDS_ + lc) * 4, A + (size_t)(m0 + r) * Cv + k0 + lc);
                cp16(sB + (r * LDS_ + lc) * 4, B + (size_t)(n0 + r) * Cv + k0 + lc);
            }
            asm volatile("cp.async.commit_group;");
            asm volatile("cp.async.wait_group 1;");
        } else {
            asm volatile("cp.async.wait_group 0;");
        }
        __syncthreads();

        const uint32_t base = sb + (it & 1) * STGB;
        const uint32_t sA = base, sB = base + ABUF;

        #pragma unroll
        for (int ks = 0; ks < 4; ++ks) {
            const int kk = ks * 8;
            uint32_t af[4][4], bf[4][2];

            // A fragments: 4 x ldmatrix.x4 (rows wm+mf*16+(lane&15), col kk+4*(lane>>4))
            #pragma unroll
            for (int mf = 0; mf < 4; ++mf) {
                int row = wm + mf * 16 + (lane & 15);
                int col = kk + ((lane >> 4) << 2);
                uint32_t addr = sA + (row * LDS_ + col) * 4;
                asm volatile("ldmatrix.sync.aligned.m8n8.x4.shared.b16 {%0,%1,%2,%3}, [%4];"
                             : "=r"(af[mf][0]), "=r"(af[mf][1]),
                               "=r"(af[mf][2]), "=r"(af[mf][3]) : "r"(addr));
            }
            // B fragments: 2 x ldmatrix.x4 covering 2 n-frags each
            #pragma unroll
            for (int np = 0; np < 2; ++np) {
                int row = wn + np * 16 + ((lane & 16) >> 1) + (lane & 7);
                int col = kk + ((lane & 8) >> 1);
                uint32_t addr = sB + (row * LDS_ + col) * 4;
                uint32_t r0, r1, r2, r3;
                asm volatile("ldmatrix.sync.aligned.m8n8.x4.shared.b16 {%0,%1,%2,%3}, [%4];"
                             : "=r"(r0), "=r"(r1), "=r"(r2), "=r"(r3) : "r"(addr));
                bf[np*2+0][0] = r0; bf[np*2+0][1] = r1;
                bf[np*2+1][0] = r2; bf[np*2+1][1] = r3;
            }

            #pragma unroll
            for (int mf = 0; mf < 4; ++mf)
                #pragma unroll
                for (int nf = 0; nf < 4; ++nf)
                    mma_tf32(acc[mf][nf], af[mf], bf[nf]);
        }
        __syncthreads();
    }

    // ---- epilogue: fragment -> gmem (float2 stores)
    const int rA = lane >> 2;
    const int cA = (lane & 3) * 2;
    #pragma unroll
    for (int mf = 0; mf < 4; ++mf)
        #pragma unroll
        for (int nf = 0; nf < 4; ++nf) {
            int row = m0 + wm + mf * 16 + rA;
            int col = n0 + wn + nf * 8 + cA;
            *(float2*)(C + (size_t)row * Cv + col) =
                make_float2(acc[mf][nf][0], acc[mf][nf][1]);
            *(float2*)(C + (size_t)(row + 8) * Cv + col) =
                make_float2(acc[mf][nf][2], acc[mf][nf][3]);
        }
}

// ---------------------------------------------------------------------------
// Causal flash attention (fp32 FFMA), output rounded to tf32
// ---------------------------------------------------------------------------
__global__ __launch_bounds__(256)
void flash_causal(const float* __restrict__ Qg, const float* __restrict__ Kg,
                  const float* __restrict__ Vg, float* __restrict__ Og)
{
    extern __shared__ float sm[];
    float* Qs  = sm;
    float* Vs  = sm + 64 * PADR;
    float* KtP = sm + 2 * 64 * PADR;

    const int tid = threadIdx.x;
    const int tx = tid & 15;
    const int ty = tid >> 4;
    const int qt = blockIdx.x;
    const int bh = blockIdx.y;
    const int b  = bh >> 4;
    const int h  = bh & 15;
    const int q0 = qt * 64;
    const size_t base = ((size_t)b * Tv) * Cv + (size_t)h * Dv;

    #pragma unroll
    for (int it = 0; it < 16; ++it) {
        int e = tid + it * 256;
        int d = e & 63, r = e >> 6;
        Qs[r * PADR + d] = Qg[base + (size_t)(q0 + r) * Cv + d];
    }

    float m[4], l[4], acc[4][4];
    #pragma unroll
    for (int i = 0; i < 4; i++) {
        m[i] = -3.0e38f; l[i] = 0.f;
        #pragma unroll
        for (int j = 0; j < 4; j++) acc[i][j] = 0.f;
    }
    __syncthreads();

    const float SC = 0.125f;

    for (int kt = 0; kt <= qt; ++kt) {
        const int k0 = kt * 64;

        #pragma unroll
        for (int it = 0; it < 16; ++it) {
            int e = tid + it * 256;
            int d = e & 63, r = e >> 6;
            size_t g = base + (size_t)(k0 + r) * Cv + d;
            KtP[d * PADR + r] = Kg[g];
            Vs[r * PADR + d]  = Vg[g];
        }
        __syncthreads();

        float s[4][4];
        #pragma unroll
        for (int i = 0; i < 4; i++)
            #pragma unroll
            for (int j = 0; j < 4; j++) s[i][j] = 0.f;

        #pragma unroll 8
        for (int d = 0; d < 64; ++d) {
            float4 kv = *(const float4*)&KtP[d * PADR + tx * 4];
            float bb[4] = {kv.x, kv.y, kv.z, kv.w};
            float aa[4];
            #pragma unroll
            for (int i = 0; i < 4; i++) aa[i] = Qs[(ty*4 + i) * PADR + d];
            #pragma unroll
            for (int i = 0; i < 4; i++)
                #pragma unroll
                for (int j = 0; j < 4; j++)
                    s[i][j] = fmaf(aa[i], bb[j], s[i][j]);
        }

        const bool diag = (kt == qt);
        #pragma unroll
        for (int i = 0; i < 4; i++) {
            const int qi = q0 + ty*4 + i;
            #pragma unroll
            for (int j = 0; j < 4; j++) {
                float sv = s[i][j] * SC;
                if (diag && (k0 + tx*4 + j > qi)) sv = -1.0e30f;
                s[i][j] = sv;
            }
        }

        #pragma unroll
        for (int i = 0; i < 4; i++) {
            float mx = fmaxf(fmaxf(s[i][0], s[i][1]), fmaxf(s[i][2], s[i][3]));
            #pragma unroll
            for (int off = 1; off < 16; off <<= 1)
                mx = fmaxf(mx, __shfl_xor_sync(0xffffffffu, mx, off));
            float nm = fmaxf(m[i], mx);
            float rs = 0.f;
            #pragma unroll
            for (int j = 0; j < 4; j++) {
                float p = __expf(s[i][j] - nm);
                s[i][j] = p;
                rs += p;
            }
            #pragma unroll
            for (int off = 1; off < 16; off <<= 1)
                rs += __shfl_xor_sync(0xffffffffu, rs, off);
            float al = __expf(m[i] - nm);
            l[i] = l[i] * al + rs;
            m[i] = nm;
            #pragma unroll
            for (int j = 0; j < 4; j++) acc[i][j] *= al;
        }

        __syncthreads();
        #pragma unroll
        for (int i = 0; i < 4; i++)
            *(float4*)&KtP[(ty*4 + i) * PADR + tx*4] =
                make_float4(s[i][0], s[i][1], s[i][2], s[i][3]);
        __syncthreads();

        #pragma unroll 8
        for (int j = 0; j < 64; ++j) {
            float4 vv = *(const float4*)&Vs[j * PADR + tx * 4];
            float pp[4];
            #pragma unroll
            for (int i = 0; i < 4; i++) pp[i] = KtP[(ty*4 + i) * PADR + j];
            #pragma unroll
            for (int i = 0; i < 4; i++) {
                acc[i][0] = fmaf(pp[i], vv.x, acc[i][0]);
                acc[i][1] = fmaf(pp[i], vv.y, acc[i][1]);
                acc[i][2] = fmaf(pp[i], vv.z, acc[i][2]);
                acc[i][3] = fmaf(pp[i], vv.w, acc[i][3]);
            }
        }
        __syncthreads();
    }

    #pragma unroll
    for (int i = 0; i < 4; i++) {
        float inv = 1.0f / l[i];
        int r = q0 + ty*4 + i;
        float o0 = acc[i][0]*inv, o1 = acc[i][1]*inv, o2 = acc[i][2]*inv, o3 = acc[i][3]*inv;
        uint32_t u0, u1, u2, u3;
        asm("cvt.rn.tf32.f32 %0, %1;" : "=r"(u0) : "f"(o0));
        asm("cvt.rn.tf32.f32 %0, %1;" : "=r"(u1) : "f"(o1));
        asm("cvt.rn.tf32.f32 %0, %1;" : "=r"(u2) : "f"(o2));
        asm("cvt.rn.tf32.f32 %0, %1;" : "=r"(u3) : "f"(o3));
        *(float4*)&Og[base + (size_t)r * Cv + tx*4] =
            make_float4(__uint_as_float(u0), __uint_as_float(u1),
                        __uint_as_float(u2), __uint_as_float(u3));
    }
}

// ---------------------------------------------------------------------------
extern "C" void kernel_launch(void* const* d_in, const int* in_sizes, int n_in,
                              void* d_out, int out_size)
{
    const float* x  = (const float*)d_in[0];
    const float* wq = (const float*)d_in[1];
    const float* wk = (const float*)d_in[2];
    const float* wv = (const float*)d_in[3];
    const float* wo = (const float*)d_in[4];
    float* out = (float*)d_out;

    float *qp, *kp, *vp, *ap, *xr, *wr;
    cudaGetSymbolAddress((void**)&qp, g_q);
    cudaGetSymbolAddress((void**)&kp, g_k);
    cudaGetSymbolAddress((void**)&vp, g_v);
    cudaGetSymbolAddress((void**)&ap, g_att);
    cudaGetSymbolAddress((void**)&xr, g_xr);
    cudaGetSymbolAddress((void**)&wr, g_wr);

    // round inputs to tf32 (RN) so in-MMA truncation is exact
    round_tf32_k<<<(Mv*Cv/4 + 255)/256, 256>>>((const float4*)x,  (float4*)xr, Mv*Cv/4);
    round_tf32_k<<<(Cv*Cv/4 + 255)/256, 256>>>((const float4*)wq, (float4*)(wr + 0*(size_t)Cv*Cv), Cv*Cv/4);
    round_tf32_k<<<(Cv*Cv/4 + 255)/256, 256>>>((const float4*)wk, (float4*)(wr + 1*(size_t)Cv*Cv), Cv*Cv/4);
    round_tf32_k<<<(Cv*Cv/4 + 255)/256, 256>>>((const float4*)wv, (float4*)(wr + 2*(size_t)Cv*Cv), Cv*Cv/4);
    round_tf32_k<<<(Cv*Cv/4 + 255)/256, 256>>>((const float4*)wo, (float4*)(wr + 3*(size_t)Cv*Cv), Cv*Cv/4);

    const int gsmem = 2 * STGB;   // 73728
    cudaFuncSetAttribute(gemm_tf32, cudaFuncAttributeMaxDynamicSharedMemorySize, gsmem);

    dim3 gg(Cv/128, Mv/128);   // (8, 64)
    gemm_tf32<<<gg, 256, gsmem>>>(xr, wr + 0*(size_t)Cv*Cv, qp);
    gemm_tf32<<<gg, 256, gsmem>>>(xr, wr + 1*(size_t)Cv*Cv, kp);
    gemm_tf32<<<gg, 256, gsmem>>>(xr, wr + 2*(size_t)Cv*Cv, vp);

    const int fsmem = 3 * 64 * PADR * (int)sizeof(float);
    cudaFuncSetAttribute(flash_causal,
                         cudaFuncAttributeMaxDynamicSharedMemorySize, fsmem);
    flash_causal<<<dim3(Tv/64, Bv*Hv), 256, fsmem>>>(qp, kp, vp, ap);

    gemm_tf32<<<gg, 256, gsmem>>>(ap, wr + 3*(size_t)Cv*Cv, out);
}

// round 4
// speedup vs baseline: 3.3312x; 1.8436x over previous
#include <cuda_runtime.h>
#include <cstdint>
#include <math.h>

#define Bv 4
#define Tv 2048
#define Cv 1024
#define Hv 16
#define Dv 64
#define Mv (Bv*Tv)          // 8192 rows

// ---------------- scratch (device globals; no allocations allowed) ----------
__device__ float g_q[Mv*Cv];
__device__ float g_k[Mv*Cv];
__device__ float g_v[Mv*Cv];
__device__ float g_att[Mv*Cv];
__device__ float g_xr[Mv*Cv];        // tf32-rounded x
__device__ float g_wr[4*Cv*Cv];      // tf32-rounded wq,wk,wv,wo

__device__ __forceinline__ uint32_t smem_u32(const void* p) {
    uint32_t a;
    asm("{ .reg .u64 t; cvta.to.shared.u64 t, %1; cvt.u32.u64 %0, t; }"
        : "=r"(a) : "l"(p));
    return a;
}
__device__ __forceinline__ void cp16(uint32_t saddr, const void* gaddr) {
    asm volatile("cp.async.cg.shared.global [%0], [%1], 16;"
                 :: "r"(saddr), "l"(gaddr));
}
__device__ __forceinline__ void mma_tf32(float* d, const uint32_t* a, const uint32_t* b) {
    asm volatile("mma.sync.aligned.m16n8k8.row.col.f32.tf32.tf32.f32 "
                 "{%0,%1,%2,%3}, {%4,%5,%6,%7}, {%8,%9}, {%0,%1,%2,%3};"
                 : "+f"(d[0]), "+f"(d[1]), "+f"(d[2]), "+f"(d[3])
                 : "r"(a[0]), "r"(a[1]), "r"(a[2]), "r"(a[3]), "r"(b[0]), "r"(b[1]));
}
#define LDM_X4(r0,r1,r2,r3, addr) \
    asm volatile("ldmatrix.sync.aligned.m8n8.x4.shared.b16 {%0,%1,%2,%3}, [%4];" \
                 : "=r"(r0),"=r"(r1),"=r"(r2),"=r"(r3) : "r"(addr))
__device__ __forceinline__ float rnd_tf32(float x) {
    uint32_t u;
    asm("cvt.rn.tf32.f32 %0, %1;" : "=r"(u) : "f"(x));
    return __uint_as_float(u);
}

// ---------------------------------------------------------------------------
// elementwise round-to-tf32 (RN)
// ---------------------------------------------------------------------------
__global__ void round_tf32_k(const float4* __restrict__ in, float4* __restrict__ out, int n4)
{
    int i = blockIdx.x * blockDim.x + threadIdx.x;
    if (i >= n4) return;
    float4 v = in[i];
    out[i] = make_float4(rnd_tf32(v.x), rnd_tf32(v.y), rnd_tf32(v.z), rnd_tf32(v.w));
}

// ---------------------------------------------------------------------------
// tf32 mma.sync GEMM:  C[M,N] = A[M,K] · B[N,K]^T
// CTA 128x128, BK=32, 256 thr, cp.async double buffer. rnd: tf32-round output.
// ---------------------------------------------------------------------------
#define GBK   32
#define LDS_  36
#define ABUF  (128*LDS_*4)
#define STGB  (2*ABUF)
#define NITER (Cv/GBK)

__global__ __launch_bounds__(256)
void gemm_tf32(const float* __restrict__ A, const float* __restrict__ B,
               float* __restrict__ C, int rnd)
{
    extern __shared__ __align__(128) char smem[];
    const uint32_t sb = smem_u32(smem);
    const int tid  = threadIdx.x;
    const int wid  = tid >> 5;
    const int lane = tid & 31;
    const int m0 = blockIdx.y * 128, n0 = blockIdx.x * 128;
    const int wm = (wid >> 2) * 64;
    const int wn = (wid & 3) * 32;
    const int lr = tid >> 3;
    const int lc = (tid & 7) * 4;

    float acc[4][4][4];
    #pragma unroll
    for (int i = 0; i < 4; i++)
        #pragma unroll
        for (int j = 0; j < 4; j++)
            #pragma unroll
            for (int k = 0; k < 4; k++) acc[i][j][k] = 0.f;

    {
        const uint32_t sA = sb, sB = sb + ABUF;
        #pragma unroll
        for (int i = 0; i < 4; i++) {
            int r = lr + i * 32;
            cp16(sA + (r * LDS_ + lc) * 4, A + (size_t)(m0 + r) * Cv + lc);
            cp16(sB + (r * LDS_ + lc) * 4, B + (size_t)(n0 + r) * Cv + lc);
        }
        asm volatile("cp.async.commit_group;");
    }

    for (int it = 0; it < NITER; ++it) {
        if (it + 1 < NITER) {
            const int k0 = (it + 1) * GBK;
            const uint32_t base = sb + ((it + 1) & 1) * STGB;
            const uint32_t sA = base, sB = base + ABUF;
            #pragma unroll
            for (int i = 0; i < 4; i++) {
                int r = lr + i * 32;
                cp16(sA + (r * LDS_ + lc) * 4, A + (size_t)(m0 + r) * Cv + k0 + lc);
                cp16(sB + (r * LDS_ + lc) * 4, B + (size_t)(n0 + r) * Cv + k0 + lc);
            }
            asm volatile("cp.async.commit_group;");
            asm volatile("cp.async.wait_group 1;");
        } else {
            asm volatile("cp.async.wait_group 0;");
        }
        __syncthreads();

        const uint32_t base = sb + (it & 1) * STGB;
        const uint32_t sA = base, sB = base + ABUF;

        #pragma unroll
        for (int ks = 0; ks < 4; ++ks) {
            const int kk = ks * 8;
            uint32_t af[4][4], bf[4][2];
            #pragma unroll
            for (int mf = 0; mf < 4; ++mf) {
                int row = wm + mf * 16 + (lane & 15);
                int col = kk + ((lane >> 4) << 2);
                LDM_X4(af[mf][0], af[mf][1], af[mf][2], af[mf][3],
                       sA + (row * LDS_ + col) * 4);
            }
            #pragma unroll
            for (int np = 0; np < 2; ++np) {
                int row = wn + np * 16 + ((lane & 16) >> 1) + (lane & 7);
                int col = kk + ((lane & 8) >> 1);
                uint32_t r0, r1, r2, r3;
                LDM_X4(r0, r1, r2, r3, sB + (row * LDS_ + col) * 4);
                bf[np*2+0][0] = r0; bf[np*2+0][1] = r1;
                bf[np*2+1][0] = r2; bf[np*2+1][1] = r3;
            }
            #pragma unroll
            for (int mf = 0; mf < 4; ++mf)
                #pragma unroll
                for (int nf = 0; nf < 4; ++nf)
                    mma_tf32(acc[mf][nf], af[mf], bf[nf]);
        }
        __syncthreads();
    }

    const int rA = lane >> 2;
    const int cA = (lane & 3) * 2;
    #pragma unroll
    for (int mf = 0; mf < 4; ++mf)
        #pragma unroll
        for (int nf = 0; nf < 4; ++nf) {
            int row = m0 + wm + mf * 16 + rA;
            int col = n0 + wn + nf * 8 + cA;
            float v0 = acc[mf][nf][0], v1 = acc[mf][nf][1];
            float v2 = acc[mf][nf][2], v3 = acc[mf][nf][3];
            if (rnd) { v0 = rnd_tf32(v0); v1 = rnd_tf32(v1);
                       v2 = rnd_tf32(v2); v3 = rnd_tf32(v3); }
            *(float2*)(C + (size_t)row * Cv + col)       = make_float2(v0, v1);
            *(float2*)(C + (size_t)(row + 8) * Cv + col) = make_float2(v2, v3);
        }
}

// ---------------------------------------------------------------------------
// Causal flash attention with mma.sync tf32.
// CTA: 64 query rows, 4 warps (16 rows each), BN=64 key tiles,
// cp.async double-buffered K/V, P via warp-private smem + ldmatrix,
// V B-frags via scalar LDS from natural-layout smem.
// ---------------------------------------------------------------------------
#define FPAD 68
#define FT   (64*FPAD)     // floats per tile buffer

__global__ __launch_bounds__(128)
void flash_mma(const float* __restrict__ Qg, const float* __restrict__ Kg,
               const float* __restrict__ Vg, float* __restrict__ Og)
{
    extern __shared__ __align__(16) float fs[];
    float* Vsm = fs + 3 * FT;                 // [2][FT] natural [j][d]
    const uint32_t sQ = smem_u32(fs);         // Qs  [FT]
    const uint32_t sK = sQ + FT * 4;          // Ks  [2][FT]
    const uint32_t sP = sQ + 5 * FT * 4;      // Ps  [FT]

    const int tid = threadIdx.x;
    const int wid = tid >> 5, lane = tid & 31;
    const int g = lane >> 2, t = lane & 3;
    const int qt = blockIdx.x, bh = blockIdx.y;
    const int b = bh >> 4, h = bh & 15;
    const int q0 = qt * 64;
    const size_t base = (size_t)b * Tv * Cv + (size_t)h * Dv;

    // prologue: Q + tile 0 (K,V) via cp.async
    {
        const float* qb = Qg + base + (size_t)q0 * Cv;
        const float* kb = Kg + base;
        const float* vb = Vg + base;
        #pragma unroll
        for (int i = 0; i < 8; i++) {
            int id = tid + i * 128, r = id >> 4, c = (id & 15) * 4;
            cp16(sQ + (r * FPAD + c) * 4, qb + (size_t)r * Cv + c);
            cp16(sK + (r * FPAD + c) * 4, kb + (size_t)r * Cv + c);
            cp16(sK + (2 * FT + r * FPAD + c) * 4, vb + (size_t)r * Cv + c);
        }
        asm volatile("cp.async.commit_group;");
    }

    float oacc[8][4];
    #pragma unroll
    for (int i = 0; i < 8; i++)
        #pragma unroll
        for (int j = 0; j < 4; j++) oacc[i][j] = 0.f;
    float m0 = -1e30f, m1 = -1e30f, l0 = 0.f, l1 = 0.f;
    uint32_t qf[8][4];

    for (int kt = 0; kt <= qt; ++kt) {
        asm volatile("cp.async.wait_group 0;");
        __syncthreads();
        if (kt < qt) {     // prefetch next K/V tile into the other buffer
            int nb = (kt + 1) & 1;
            const float* kb = Kg + base + (size_t)((kt + 1) * 64) * Cv;
            const float* vb = Vg + base + (size_t)((kt + 1) * 64) * Cv;
            #pragma unroll
            for (int i = 0; i < 8; i++) {
                int id = tid + i * 128, r = id >> 4, c = (id & 15) * 4;
                cp16(sK + (nb * FT + r * FPAD + c) * 4, kb + (size_t)r * Cv + c);
                cp16(sK + ((2 + nb) * FT + r * FPAD + c) * 4, vb + (size_t)r * Cv + c);
            }
            asm volatile("cp.async.commit_group;");
        }
        if (kt == 0) {     // preload Q fragments, fold in softmax scale (2^-3, tf32-exact)
            #pragma unroll
            for (int ks = 0; ks < 8; ks++) {
                int row = wid * 16 + (lane & 15);
                int col = ks * 8 + ((lane >> 4) << 2);
                LDM_X4(qf[ks][0], qf[ks][1], qf[ks][2], qf[ks][3],
                       sQ + (row * FPAD + col) * 4);
                #pragma unroll
                for (int i = 0; i < 4; i++)
                    qf[ks][i] = __float_as_uint(__uint_as_float(qf[ks][i]) * 0.125f);
            }
        }
        const uint32_t sKb = sK + (kt & 1) * FT * 4;
        const float* Vb = Vsm + (kt & 1) * FT;

        // ---- S = Q K^T
        float sacc[8][4];
        #pragma unroll
        for (int i = 0; i < 8; i++)
            #pragma unroll
            for (int j = 0; j < 4; j++) sacc[i][j] = 0.f;

        #pragma unroll
        for (int ks = 0; ks < 8; ks++) {
            uint32_t bf[8][2];
            #pragma unroll
            for (int np = 0; np < 4; np++) {
                int row = np * 16 + ((lane & 16) >> 1) + (lane & 7);
                int col = ks * 8 + ((lane & 8) >> 1);
                uint32_t r0, r1, r2, r3;
                LDM_X4(r0, r1, r2, r3, sKb + (row * FPAD + col) * 4);
                bf[np*2+0][0] = r0; bf[np*2+0][1] = r1;
                bf[np*2+1][0] = r2; bf[np*2+1][1] = r3;
            }
            #pragma unroll
            for (int nf = 0; nf < 8; nf++) mma_tf32(sacc[nf], qf[ks], bf[nf]);
        }

        // ---- causal mask (diagonal tile only; local coords since q0==k0)
        if (kt == qt) {
            int r0l = wid * 16 + g, r1l = r0l + 8;
            #pragma unroll
            for (int nf = 0; nf < 8; nf++) {
                int c0 = nf * 8 + 2 * t;
                if (c0     > r0l) sacc[nf][0] = -1e30f;
                if (c0 + 1 > r0l) sacc[nf][1] = -1e30f;
                if (c0     > r1l) sacc[nf][2] = -1e30f;
                if (c0 + 1 > r1l) sacc[nf][3] = -1e30f;
            }
        }

        // ---- online softmax (rows g and g+8, quad-wide reductions)
        float mx0 = -1e30f, mx1 = -1e30f;
        #pragma unroll
        for (int nf = 0; nf < 8; nf++) {
            mx0 = fmaxf(mx0, fmaxf(sacc[nf][0], sacc[nf][1]));
            mx1 = fmaxf(mx1, fmaxf(sacc[nf][2], sacc[nf][3]));
        }
        #pragma unroll
        for (int off = 1; off < 4; off <<= 1) {
            mx0 = fmaxf(mx0, __shfl_xor_sync(0xffffffffu, mx0, off));
            mx1 = fmaxf(mx1, __shfl_xor_sync(0xffffffffu, mx1, off));
        }
        float nm0 = fmaxf(m0, mx0), nm1 = fmaxf(m1, mx1);
        float al0 = __expf(m0 - nm0), al1 = __expf(m1 - nm1);
        float rs0 = 0.f, rs1 = 0.f;
        #pragma unroll
        for (int nf = 0; nf < 8; nf++) {
            float p0 = rnd_tf32(__expf(sacc[nf][0] - nm0));
            float p1 = rnd_tf32(__expf(sacc[nf][1] - nm0));
            float p2 = rnd_tf32(__expf(sacc[nf][2] - nm1));
            float p3 = rnd_tf32(__expf(sacc[nf][3] - nm1));
            sacc[nf][0] = p0; sacc[nf][1] = p1; sacc[nf][2] = p2; sacc[nf][3] = p3;
            rs0 += p0 + p1; rs1 += p2 + p3;
        }
        #pragma unroll
        for (int off = 1; off < 4; off <<= 1) {
            rs0 += __shfl_xor_sync(0xffffffffu, rs0, off);
            rs1 += __shfl_xor_sync(0xffffffffu, rs1, off);
        }
        l0 = l0 * al0 + rs0; m0 = nm0;
        l1 = l1 * al1 + rs1; m1 = nm1;
        #pragma unroll
        for (int nf = 0; nf < 8; nf++) {
            oacc[nf][0] *= al0; oacc[nf][1] *= al0;
            oacc[nf][2] *= al1; oacc[nf][3] *= al1;
        }

        // ---- P -> warp-private smem rows, then ldmatrix as A of PV
        __syncwarp();
        {
            float* Pw = fs + 5 * FT;
            int pr0 = wid * 16 + g, pr1 = pr0 + 8;
            #pragma unroll
            for (int nf = 0; nf < 8; nf++) {
                *(float2*)&Pw[pr0 * FPAD + nf * 8 + 2 * t] = make_float2(sacc[nf][0], sacc[nf][1]);
                *(float2*)&Pw[pr1 * FPAD + nf * 8 + 2 * t] = make_float2(sacc[nf][2], sacc[nf][3]);
            }
        }
        __syncwarp();

        // ---- O += P V   (B-frags: scalar LDS from natural V; b0=(k=t,n=g), b1=(k=t+4,n=g))
        #pragma unroll
        for (int ks = 0; ks < 8; ks++) {
            uint32_t af[4];
            int row = wid * 16 + (lane & 15);
            int col = ks * 8 + ((lane >> 4) << 2);
            LDM_X4(af[0], af[1], af[2], af[3], sP + (row * FPAD + col) * 4);
            #pragma unroll
            for (int nf = 0; nf < 8; nf++) {
                uint32_t bv[2];
                bv[0] = __float_as_uint(Vb[(ks * 8 + t)     * FPAD + nf * 8 + g]);
                bv[1] = __float_as_uint(Vb[(ks * 8 + t + 4) * FPAD + nf * 8 + g]);
                mma_tf32(oacc[nf], af, bv);
            }
        }
    }

    // ---- epilogue: normalize, round to tf32, store
    float inv0 = 1.f / l0, inv1 = 1.f / l1;
    int r0g = q0 + wid * 16 + g, r1g = r0g + 8;
    #pragma unroll
    for (int nf = 0; nf < 8; nf++) {
        int c = nf * 8 + 2 * t;
        *(float2*)(Og + base + (size_t)r0g * Cv + c) =
            make_float2(rnd_tf32(oacc[nf][0] * inv0), rnd_tf32(oacc[nf][1] * inv0));
        *(float2*)(Og + base + (size_t)r1g * Cv + c) =
            make_float2(rnd_tf32(oacc[nf][2] * inv1), rnd_tf32(oacc[nf][3] * inv1));
    }
}

// ---------------------------------------------------------------------------
extern "C" void kernel_launch(void* const* d_in, const int* in_sizes, int n_in,
                              void* d_out, int out_size)
{
    const float* x  = (const float*)d_in[0];
    const float* wq = (const float*)d_in[1];
    const float* wk = (const float*)d_in[2];
    const float* wv = (const float*)d_in[3];
    const float* wo = (const float*)d_in[4];
    float* out = (float*)d_out;

    float *qp, *kp, *vp, *ap, *xr, *wr;
    cudaGetSymbolAddress((void**)&qp, g_q);
    cudaGetSymbolAddress((void**)&kp, g_k);
    cudaGetSymbolAddress((void**)&vp, g_v);
    cudaGetSymbolAddress((void**)&ap, g_att);
    cudaGetSymbolAddress((void**)&xr, g_xr);
    cudaGetSymbolAddress((void**)&wr, g_wr);

    round_tf32_k<<<(Mv*Cv/4 + 255)/256, 256>>>((const float4*)x,  (float4*)xr, Mv*Cv/4);
    round_tf32_k<<<(Cv*Cv/4 + 255)/256, 256>>>((const float4*)wq, (float4*)(wr + 0*(size_t)Cv*Cv), Cv*Cv/4);
    round_tf32_k<<<(Cv*Cv/4 + 255)/256, 256>>>((const float4*)wk, (float4*)(wr + 1*(size_t)Cv*Cv), Cv*Cv/4);
    round_tf32_k<<<(Cv*Cv/4 + 255)/256, 256>>>((const float4*)wv, (float4*)(wr + 2*(size_t)Cv*Cv), Cv*Cv/4);
    round_tf32_k<<<(Cv*Cv/4 + 255)/256, 256>>>((const float4*)wo, (float4*)(wr + 3*(size_t)Cv*Cv), Cv*Cv/4);

    const int gsmem = 2 * STGB;
    cudaFuncSetAttribute(gemm_tf32, cudaFuncAttributeMaxDynamicSharedMemorySize, gsmem);

    dim3 gg(Cv/128, Mv/128);
    gemm_tf32<<<gg, 256, gsmem>>>(xr, wr + 0*(size_t)Cv*Cv, qp, 1);
    gemm_tf32<<<gg, 256, gsmem>>>(xr, wr + 1*(size_t)Cv*Cv, kp, 1);
    gemm_tf32<<<gg, 256, gsmem>>>(xr, wr + 2*(size_t)Cv*Cv, vp, 1);

    const int fsmem = 6 * FT * (int)sizeof(float);   // 104448
    cudaFuncSetAttribute(flash_mma, cudaFuncAttributeMaxDynamicSharedMemorySize, fsmem);
    flash_mma<<<dim3(Tv/64, Bv*Hv), 128, fsmem>>>(qp, kp, vp, ap);

    gemm_tf32<<<gg, 256, gsmem>>>(ap, wr + 3*(size_t)Cv*Cv, out, 0);
}

// round 5
// speedup vs baseline: 3.4778x; 1.0440x over previous
#include <cuda_runtime.h>
#include <cstdint>
#include <math.h>

#define Bv 4
#define Tv 2048
#define Cv 1024
#define Hv 16
#define Dv 64
#define Mv (Bv*Tv)          // 8192 rows

// ---------------- scratch (device globals; no allocations allowed) ----------
__device__ float g_q[Mv*Cv];
__device__ float g_k[Mv*Cv];
__device__ float g_v[Mv*Cv];
__device__ float g_att[Mv*Cv];
__device__ float g_xr[Mv*Cv];        // tf32-rounded x
__device__ float g_wr[4*Cv*Cv];      // tf32-rounded wq,wk,wv,wo (contiguous)

__device__ __forceinline__ uint32_t smem_u32(const void* p) {
    uint32_t a;
    asm("{ .reg .u64 t; cvta.to.shared.u64 t, %1; cvt.u32.u64 %0, t; }"
        : "=r"(a) : "l"(p));
    return a;
}
__device__ __forceinline__ void cp16(uint32_t saddr, const void* gaddr) {
    asm volatile("cp.async.cg.shared.global [%0], [%1], 16;"
                 :: "r"(saddr), "l"(gaddr));
}
__device__ __forceinline__ void mma_tf32(float* d, const uint32_t* a, const uint32_t* b) {
    asm volatile("mma.sync.aligned.m16n8k8.row.col.f32.tf32.tf32.f32 "
                 "{%0,%1,%2,%3}, {%4,%5,%6,%7}, {%8,%9}, {%0,%1,%2,%3};"
                 : "+f"(d[0]), "+f"(d[1]), "+f"(d[2]), "+f"(d[3])
                 : "r"(a[0]), "r"(a[1]), "r"(a[2]), "r"(a[3]), "r"(b[0]), "r"(b[1]));
}
#define LDM_X4(r0,r1,r2,r3, addr) \
    asm volatile("ldmatrix.sync.aligned.m8n8.x4.shared.b16 {%0,%1,%2,%3}, [%4];" \
                 : "=r"(r0),"=r"(r1),"=r"(r2),"=r"(r3) : "r"(addr))
__device__ __forceinline__ float rnd_tf32(float x) {
    uint32_t u;
    asm("cvt.rn.tf32.f32 %0, %1;" : "=r"(u) : "f"(x));
    return __uint_as_float(u);
}

// ---------------------------------------------------------------------------
__global__ void round_tf32_k(const float4* __restrict__ in, float4* __restrict__ out, int n4)
{
    int i = blockIdx.x * blockDim.x + threadIdx.x;
    if (i >= n4) return;
    float4 v = in[i];
    out[i] = make_float4(rnd_tf32(v.x), rnd_tf32(v.y), rnd_tf32(v.z), rnd_tf32(v.w));
}

// ---------------------------------------------------------------------------
// tf32 mma.sync GEMM:  C[M,N] = A[M,K] · B[N,K]^T
// CTA 128x128, BK=32, 256 thr, cp.async double buffer.
// If C1 != null: fused QKV mode, output segment chosen by n-block.
// ---------------------------------------------------------------------------
#define GBK   32
#define LDS_  36
#define ABUF  (128*LDS_*4)
#define STGB  (2*ABUF)
#define NITER (Cv/GBK)

__global__ __launch_bounds__(256)
void gemm_tf32(const float* __restrict__ A, const float* __restrict__ B,
               float* __restrict__ C0, float* __restrict__ C1,
               float* __restrict__ C2, int rnd)
{
    extern __shared__ __align__(128) char smem[];
    const uint32_t sb = smem_u32(smem);
    const int tid  = threadIdx.x;
    const int wid  = tid >> 5;
    const int lane = tid & 31;
    const int m0 = blockIdx.y * 128, n0 = blockIdx.x * 128;
    const int wm = (wid >> 2) * 64;
    const int wn = (wid & 3) * 32;
    const int lr = tid >> 3;
    const int lc = (tid & 7) * 4;

    float acc[4][4][4];
    #pragma unroll
    for (int i = 0; i < 4; i++)
        #pragma unroll
        for (int j = 0; j < 4; j++)
            #pragma unroll
            for (int k = 0; k < 4; k++) acc[i][j][k] = 0.f;

    {
        const uint32_t sA = sb, sB = sb + ABUF;
        #pragma unroll
        for (int i = 0; i < 4; i++) {
            int r = lr + i * 32;
            cp16(sA + (r * LDS_ + lc) * 4, A + (size_t)(m0 + r) * Cv + lc);
            cp16(sB + (r * LDS_ + lc) * 4, B + (size_t)(n0 + r) * Cv + lc);
        }
        asm volatile("cp.async.commit_group;");
    }

    for (int it = 0; it < NITER; ++it) {
        if (it + 1 < NITER) {
            const int k0 = (it + 1) * GBK;
            const uint32_t base = sb + ((it + 1) & 1) * STGB;
            const uint32_t sA = base, sB = base + ABUF;
            #pragma unroll
            for (int i = 0; i < 4; i++) {
                int r = lr + i * 32;
                cp16(sA + (r * LDS_ + lc) * 4, A + (size_t)(m0 + r) * Cv + k0 + lc);
                cp16(sB + (r * LDS_ + lc) * 4, B + (size_t)(n0 + r) * Cv + k0 + lc);
            }
            asm volatile("cp.async.commit_group;");
            asm volatile("cp.async.wait_group 1;");
        } else {
            asm volatile("cp.async.wait_group 0;");
        }
        __syncthreads();

        const uint32_t base = sb + (it & 1) * STGB;
        const uint32_t sA = base, sB = base + ABUF;

        #pragma unroll
        for (int ks = 0; ks < 4; ++ks) {
            const int kk = ks * 8;
            uint32_t af[4][4], bf[4][2];
            #pragma unroll
            for (int mf = 0; mf < 4; ++mf) {
                int row = wm + mf * 16 + (lane & 15);
                int col = kk + ((lane >> 4) << 2);
                LDM_X4(af[mf][0], af[mf][1], af[mf][2], af[mf][3],
                       sA + (row * LDS_ + col) * 4);
            }
            #pragma unroll
            for (int np = 0; np < 2; ++np) {
                int row = wn + np * 16 + ((lane & 16) >> 1) + (lane & 7);
                int col = kk + ((lane & 8) >> 1);
                uint32_t r0, r1, r2, r3;
                LDM_X4(r0, r1, r2, r3, sB + (row * LDS_ + col) * 4);
                bf[np*2+0][0] = r0; bf[np*2+0][1] = r1;
                bf[np*2+1][0] = r2; bf[np*2+1][1] = r3;
            }
            #pragma unroll
            for (int mf = 0; mf < 4; ++mf)
                #pragma unroll
                for (int nf = 0; nf < 4; ++nf)
                    mma_tf32(acc[mf][nf], af[mf], bf[nf]);
        }
        __syncthreads();
    }

    // output segment select (fused QKV)
    float* C = C0; int nn = n0;
    if (C1 != nullptr && n0 >= 1024) {
        C = (n0 >= 2048) ? C2 : C1;
        nn = n0 & 1023;
    }

    const int rA = lane >> 2;
    const int cA = (lane & 3) * 2;
    #pragma unroll
    for (int mf = 0; mf < 4; ++mf)
        #pragma unroll
        for (int nf = 0; nf < 4; ++nf) {
            int row = m0 + wm + mf * 16 + rA;
            int col = nn + wn + nf * 8 + cA;
            float v0 = acc[mf][nf][0], v1 = acc[mf][nf][1];
            float v2 = acc[mf][nf][2], v3 = acc[mf][nf][3];
            if (rnd) { v0 = rnd_tf32(v0); v1 = rnd_tf32(v1);
                       v2 = rnd_tf32(v2); v3 = rnd_tf32(v3); }
            *(float2*)(C + (size_t)row * Cv + col)       = make_float2(v0, v1);
            *(float2*)(C + (size_t)(row + 8) * Cv + col) = make_float2(v2, v3);
        }
}

// ---------------------------------------------------------------------------
// Causal flash attention with mma.sync tf32.
// 64 q-rows/CTA, 4 warps, BN=64, double-buffered K/V via cp.async.
// V transposed in smem -> ldmatrix B-frags for PV. P reuses current K buffer.
// smem = 6*FT = 104448 B -> 2 CTAs/SM.
// ---------------------------------------------------------------------------
#define FPAD 68
#define FT   (64*FPAD)

__global__ __launch_bounds__(128, 2)
void flash_mma(const float* __restrict__ Qg, const float* __restrict__ Kg,
               const float* __restrict__ Vg, float* __restrict__ Og)
{
    extern __shared__ __align__(16) float fs[];
    const uint32_t sQ  = smem_u32(fs);        // Q       [FT]
    const uint32_t sK0 = sQ + FT * 4;         // K       [2][FT] (cur buf reused for P)
    const uint32_t sV0 = sQ + 3 * FT * 4;     // V nat   [2][FT]
    const uint32_t sVt = sQ + 5 * FT * 4;     // V^T     [FT]
    float* Vt = fs + 5 * FT;

    const int tid = threadIdx.x;
    const int wid = tid >> 5, lane = tid & 31;
    const int g = lane >> 2, t = lane & 3;
    const int qt = blockIdx.x, bh = blockIdx.y;
    const int b = bh >> 4, h = bh & 15;
    const int q0 = qt * 64;
    const size_t base = (size_t)b * Tv * Cv + (size_t)h * Dv;

    // prologue: Q + tile 0 (K,V)
    {
        const float* qb = Qg + base + (size_t)q0 * Cv;
        const float* kb = Kg + base;
        const float* vb = Vg + base;
        #pragma unroll
        for (int i = 0; i < 8; i++) {
            int id = tid + i * 128, r = id >> 4, c = (id & 15) * 4;
            cp16(sQ  + (r * FPAD + c) * 4, qb + (size_t)r * Cv + c);
            cp16(sK0 + (r * FPAD + c) * 4, kb + (size_t)r * Cv + c);
            cp16(sV0 + (r * FPAD + c) * 4, vb + (size_t)r * Cv + c);
        }
        asm volatile("cp.async.commit_group;");
    }

    float oacc[8][4];
    #pragma unroll
    for (int i = 0; i < 8; i++)
        #pragma unroll
        for (int j = 0; j < 4; j++) oacc[i][j] = 0.f;
    float m0 = -1e30f, m1 = -1e30f, l0 = 0.f, l1 = 0.f;
    uint32_t qf[8][4];

    for (int kt = 0; kt <= qt; ++kt) {
        const int cur = kt & 1;
        asm volatile("cp.async.wait_group 0;");
        __syncthreads();
        if (kt < qt) {
            int nb = cur ^ 1;
            const float* kb = Kg + base + (size_t)((kt + 1) * 64) * Cv;
            const float* vb = Vg + base + (size_t)((kt + 1) * 64) * Cv;
            #pragma unroll
            for (int i = 0; i < 8; i++) {
                int id = tid + i * 128, r = id >> 4, c = (id & 15) * 4;
                cp16(sK0 + (nb * FT + r * FPAD + c) * 4, kb + (size_t)r * Cv + c);
                cp16(sV0 + (nb * FT + r * FPAD + c) * 4, vb + (size_t)r * Cv + c);
            }
            asm volatile("cp.async.commit_group;");
        }
        if (kt == 0) {   // Q fragments, softmax scale 2^-3 folded in (tf32-exact)
            #pragma unroll
            for (int ks = 0; ks < 8; ks++) {
                int row = wid * 16 + (lane & 15);
                int col = ks * 8 + ((lane >> 4) << 2);
                LDM_X4(qf[ks][0], qf[ks][1], qf[ks][2], qf[ks][3],
                       sQ + (row * FPAD + col) * 4);
                #pragma unroll
                for (int i = 0; i < 4; i++)
                    qf[ks][i] = __float_as_uint(__uint_as_float(qf[ks][i]) * 0.125f);
            }
        }
        const uint32_t sKb = sK0 + cur * FT * 4;
        const float*   Vn  = fs + 3 * FT + cur * FT;   // natural V (cur)

        // ---- transpose V (cur) -> Vt  [d][j]
        {
            int j = tid >> 1, dbase = (tid & 1) * 32;
            #pragma unroll
            for (int i = 0; i < 8; i++) {
                float4 v = *(const float4*)&Vn[j * FPAD + dbase + i * 4];
                Vt[(dbase + i * 4 + 0) * FPAD + j] = v.x;
                Vt[(dbase + i * 4 + 1) * FPAD + j] = v.y;
                Vt[(dbase + i * 4 + 2) * FPAD + j] = v.z;
                Vt[(dbase + i * 4 + 3) * FPAD + j] = v.w;
            }
        }

        // ---- S = Q K^T
        float sacc[8][4];
        #pragma unroll
        for (int i = 0; i < 8; i++)
            #pragma unroll
            for (int j = 0; j < 4; j++) sacc[i][j] = 0.f;

        #pragma unroll
        for (int ks = 0; ks < 8; ks++) {
            uint32_t bf[8][2];
            #pragma unroll
            for (int np = 0; np < 4; np++) {
                int row = np * 16 + ((lane & 16) >> 1) + (lane & 7);
                int col = ks * 8 + ((lane & 8) >> 1);
                uint32_t r0, r1, r2, r3;
                LDM_X4(r0, r1, r2, r3, sKb + (row * FPAD + col) * 4);
                bf[np*2+0][0] = r0; bf[np*2+0][1] = r1;
                bf[np*2+1][0] = r2; bf[np*2+1][1] = r3;
            }
            #pragma unroll
            for (int nf = 0; nf < 8; nf++) mma_tf32(sacc[nf], qf[ks], bf[nf]);
        }

        // ---- causal mask (diagonal tile only)
        if (kt == qt) {
            int r0l = wid * 16 + g, r1l = r0l + 8;
            #pragma unroll
            for (int nf = 0; nf < 8; nf++) {
                int c0 = nf * 8 + 2 * t;
                if (c0     > r0l) sacc[nf][0] = -1e30f;
                if (c0 + 1 > r0l) sacc[nf][1] = -1e30f;
                if (c0     > r1l) sacc[nf][2] = -1e30f;
                if (c0 + 1 > r1l) sacc[nf][3] = -1e30f;
            }
        }

        // ---- online softmax (register-only)
        float mx0 = -1e30f, mx1 = -1e30f;
        #pragma unroll
        for (int nf = 0; nf < 8; nf++) {
            mx0 = fmaxf(mx0, fmaxf(sacc[nf][0], sacc[nf][1]));
            mx1 = fmaxf(mx1, fmaxf(sacc[nf][2], sacc[nf][3]));
        }
        #pragma unroll
        for (int off = 1; off < 4; off <<= 1) {
            mx0 = fmaxf(mx0, __shfl_xor_sync(0xffffffffu, mx0, off));
            mx1 = fmaxf(mx1, __shfl_xor_sync(0xffffffffu, mx1, off));
        }
        float nm0 = fmaxf(m0, mx0), nm1 = fmaxf(m1, mx1);
        float al0 = __expf(m0 - nm0), al1 = __expf(m1 - nm1);
        float rs0 = 0.f, rs1 = 0.f;
        #pragma unroll
        for (int nf = 0; nf < 8; nf++) {
            float p0 = rnd_tf32(__expf(sacc[nf][0] - nm0));
            float p1 = rnd_tf32(__expf(sacc[nf][1] - nm0));
            float p2 = rnd_tf32(__expf(sacc[nf][2] - nm1));
            float p3 = rnd_tf32(__expf(sacc[nf][3] - nm1));
            sacc[nf][0] = p0; sacc[nf][1] = p1; sacc[nf][2] = p2; sacc[nf][3] = p3;
            rs0 += p0 + p1; rs1 += p2 + p3;
        }
        #pragma unroll
        for (int off = 1; off < 4; off <<= 1) {
            rs0 += __shfl_xor_sync(0xffffffffu, rs0, off);
            rs1 += __shfl_xor_sync(0xffffffffu, rs1, off);
        }
        l0 = l0 * al0 + rs0; m0 = nm0;
        l1 = l1 * al1 + rs1; m1 = nm1;
        #pragma unroll
        for (int nf = 0; nf < 8; nf++) {
            oacc[nf][0] *= al0; oacc[nf][1] *= al0;
            oacc[nf][2] *= al1; oacc[nf][3] *= al1;
        }

        // all warps done reading Kcur (S) and writing Vt
        __syncthreads();

        // ---- P -> Kcur buffer (reuse), then ldmatrix as A of PV
        {
            float* Pw = fs + FT + cur * FT;
            int pr0 = wid * 16 + g, pr1 = pr0 + 8;
            #pragma unroll
            for (int nf = 0; nf < 8; nf++) {
                *(float2*)&Pw[pr0 * FPAD + nf * 8 + 2 * t] = make_float2(sacc[nf][0], sacc[nf][1]);
                *(float2*)&Pw[pr1 * FPAD + nf * 8 + 2 * t] = make_float2(sacc[nf][2], sacc[nf][3]);
            }
        }
        __syncthreads();

        // ---- O += P V  (A = P via ldmatrix, B = Vt via ldmatrix, GEMM mapping)
        #pragma unroll
        for (int ks = 0; ks < 8; ks++) {
            uint32_t af[4];
            int row = wid * 16 + (lane & 15);
            int col = ks * 8 + ((lane >> 4) << 2);
            LDM_X4(af[0], af[1], af[2], af[3], sKb + (row * FPAD + col) * 4);
            uint32_t bf[8][2];
            #pragma unroll
            for (int np = 0; np < 4; np++) {
                int brow = np * 16 + ((lane & 16) >> 1) + (lane & 7);
                int bcol = ks * 8 + ((lane & 8) >> 1);
                uint32_t r0, r1, r2, r3;
                LDM_X4(r0, r1, r2, r3, sVt + (brow * FPAD + bcol) * 4);
                bf[np*2+0][0] = r0; bf[np*2+0][1] = r1;
                bf[np*2+1][0] = r2; bf[np*2+1][1] = r3;
            }
            #pragma unroll
            for (int nf = 0; nf < 8; nf++) mma_tf32(oacc[nf], af, bf[nf]);
        }
    }

    // ---- epilogue
    float inv0 = 1.f / l0, inv1 = 1.f / l1;
    int r0g = q0 + wid * 16 + g, r1g = r0g + 8;
    #pragma unroll
    for (int nf = 0; nf < 8; nf++) {
        int c = nf * 8 + 2 * t;
        *(float2*)(Og + base + (size_t)r0g * Cv + c) =
            make_float2(rnd_tf32(oacc[nf][0] * inv0), rnd_tf32(oacc[nf][1] * inv0));
        *(float2*)(Og + base + (size_t)r1g * Cv + c) =
            make_float2(rnd_tf32(oacc[nf][2] * inv1), rnd_tf32(oacc[nf][3] * inv1));
    }
}

// ---------------------------------------------------------------------------
extern "C" void kernel_launch(void* const* d_in, const int* in_sizes, int n_in,
                              void* d_out, int out_size)
{
    const float* x  = (const float*)d_in[0];
    const float* wq = (const float*)d_in[1];
    const float* wk = (const float*)d_in[2];
    const float* wv = (const float*)d_in[3];
    const float* wo = (const float*)d_in[4];
    float* out = (float*)d_out;

    float *qp, *kp, *vp, *ap, *xr, *wr;
    cudaGetSymbolAddress((void**)&qp, g_q);
    cudaGetSymbolAddress((void**)&kp, g_k);
    cudaGetSymbolAddress((void**)&vp, g_v);
    cudaGetSymbolAddress((void**)&ap, g_att);
    cudaGetSymbolAddress((void**)&xr, g_xr);
    cudaGetSymbolAddress((void**)&wr, g_wr);

    round_tf32_k<<<(Mv*Cv/4 + 255)/256, 256>>>((const float4*)x,  (float4*)xr, Mv*Cv/4);
    round_tf32_k<<<(Cv*Cv/4 + 255)/256, 256>>>((const float4*)wq, (float4*)(wr + 0*(size_t)Cv*Cv), Cv*Cv/4);
    round_tf32_k<<<(Cv*Cv/4 + 255)/256, 256>>>((const float4*)wk, (float4*)(wr + 1*(size_t)Cv*Cv), Cv*Cv/4);
    round_tf32_k<<<(Cv*Cv/4 + 255)/256, 256>>>((const float4*)wv, (float4*)(wr + 2*(size_t)Cv*Cv), Cv*Cv/4);
    round_tf32_k<<<(Cv*Cv/4 + 255)/256, 256>>>((const float4*)wo, (float4*)(wr + 3*(size_t)Cv*Cv), Cv*Cv/4);

    const int gsmem = 2 * STGB;
    cudaFuncSetAttribute(gemm_tf32, cudaFuncAttributeMaxDynamicSharedMemorySize, gsmem);

    // fused QKV: B = [wq; wk; wv] (3072 x 1024), outputs split per n-block
    gemm_tf32<<<dim3(24, 64), 256, gsmem>>>(xr, wr, qp, kp, vp, 1);

    const int fsmem = 6 * FT * (int)sizeof(float);   // 104448
    cudaFuncSetAttribute(flash_mma, cudaFuncAttributeMaxDynamicSharedMemorySize, fsmem);
    flash_mma<<<dim3(Tv/64, Bv*Hv), 128, fsmem>>>(qp, kp, vp, ap);

    gemm_tf32<<<dim3(8, 64), 256, gsmem>>>(ap, wr + 3*(size_t)Cv*Cv, out,
                                           nullptr, nullptr, 0);
}

// round 6
// speedup vs baseline: 3.6632x; 1.0533x over previous
#include <cuda_runtime.h>
#include <cstdint>
#include <math.h>

#define Bv 4
#define Tv 2048
#define Cv 1024
#define Hv 16
#define Dv 64
#define Mv (Bv*Tv)          // 8192 rows

// ---------------- scratch (device globals; no allocations allowed) ----------
__device__ float g_q[Mv*Cv];
__device__ float g_k[Mv*Cv];
__device__ float g_v[Mv*Cv];
__device__ float g_att[Mv*Cv];
__device__ float g_xr[Mv*Cv];        // tf32-rounded x
__device__ float g_wr[4*Cv*Cv];      // tf32-rounded wq,wk,wv,wo (contiguous)

__device__ __forceinline__ uint32_t smem_u32(const void* p) {
    uint32_t a;
    asm("{ .reg .u64 t; cvta.to.shared.u64 t, %1; cvt.u32.u64 %0, t; }"
        : "=r"(a) : "l"(p));
    return a;
}
__device__ __forceinline__ void cp16(uint32_t saddr, const void* gaddr) {
    asm volatile("cp.async.cg.shared.global [%0], [%1], 16;"
                 :: "r"(saddr), "l"(gaddr));
}
__device__ __forceinline__ void mma_tf32(float* d, const uint32_t* a, const uint32_t* b) {
    asm volatile("mma.sync.aligned.m16n8k8.row.col.f32.tf32.tf32.f32 "
                 "{%0,%1,%2,%3}, {%4,%5,%6,%7}, {%8,%9}, {%0,%1,%2,%3};"
                 : "+f"(d[0]), "+f"(d[1]), "+f"(d[2]), "+f"(d[3])
                 : "r"(a[0]), "r"(a[1]), "r"(a[2]), "r"(a[3]), "r"(b[0]), "r"(b[1]));
}
#define LDM_X4(r0,r1,r2,r3, addr) \
    asm volatile("ldmatrix.sync.aligned.m8n8.x4.shared.b16 {%0,%1,%2,%3}, [%4];" \
                 : "=r"(r0),"=r"(r1),"=r"(r2),"=r"(r3) : "r"(addr))
__device__ __forceinline__ float rnd_tf32(float x) {
    uint32_t u;
    asm("cvt.rn.tf32.f32 %0, %1;" : "=r"(u) : "f"(x));
    return __uint_as_float(u);
}

// ---------------------------------------------------------------------------
__global__ void round_tf32_k(const float4* __restrict__ in, float4* __restrict__ out, int n4)
{
    int i = blockIdx.x * blockDim.x + threadIdx.x;
    if (i >= n4) return;
    float4 v = in[i];
    out[i] = make_float4(rnd_tf32(v.x), rnd_tf32(v.y), rnd_tf32(v.z), rnd_tf32(v.w));
}

// round 4 separate weight matrices into contiguous g_wr with one launch
__global__ void round_tf32_w4(const float4* __restrict__ w0, const float4* __restrict__ w1,
                              const float4* __restrict__ w2, const float4* __restrict__ w3,
                              float4* __restrict__ out)
{
    const int per = Cv * Cv / 4;
    int i = blockIdx.x * blockDim.x + threadIdx.x;
    if (i >= 4 * per) return;
    const float4* src = (i < per) ? w0 : (i < 2*per) ? w1 : (i < 3*per) ? w2 : w3;
    float4 v = src[i & (per - 1)];
    out[i] = make_float4(rnd_tf32(v.x), rnd_tf32(v.y), rnd_tf32(v.z), rnd_tf32(v.w));
}

// ---------------------------------------------------------------------------
// tf32 mma.sync GEMM:  C[M,N] = A[M,K] · B[N,K]^T
// CTA 128x128, BK=32, 256 thr, cp.async double buffer.
// If C1 != null: fused QKV mode, output segment chosen by n-block.
// ---------------------------------------------------------------------------
#define GBK   32
#define LDS_  36
#define ABUF  (128*LDS_*4)
#define STGB  (2*ABUF)
#define NITER (Cv/GBK)

__global__ __launch_bounds__(256)
void gemm_tf32(const float* __restrict__ A, const float* __restrict__ B,
               float* __restrict__ C0, float* __restrict__ C1,
               float* __restrict__ C2, int rnd)
{
    extern __shared__ __align__(128) char smem[];
    const uint32_t sb = smem_u32(smem);
    const int tid  = threadIdx.x;
    const int wid  = tid >> 5;
    const int lane = tid & 31;
    const int m0 = blockIdx.y * 128, n0 = blockIdx.x * 128;
    const int wm = (wid >> 2) * 64;
    const int wn = (wid & 3) * 32;
    const int lr = tid >> 3;
    const int lc = (tid & 7) * 4;

    float acc[4][4][4];
    #pragma unroll
    for (int i = 0; i < 4; i++)
        #pragma unroll
        for (int j = 0; j < 4; j++)
            #pragma unroll
            for (int k = 0; k < 4; k++) acc[i][j][k] = 0.f;

    {
        const uint32_t sA = sb, sB = sb + ABUF;
        #pragma unroll
        for (int i = 0; i < 4; i++) {
            int r = lr + i * 32;
            cp16(sA + (r * LDS_ + lc) * 4, A + (size_t)(m0 + r) * Cv + lc);
            cp16(sB + (r * LDS_ + lc) * 4, B + (size_t)(n0 + r) * Cv + lc);
        }
        asm volatile("cp.async.commit_group;");
    }

    for (int it = 0; it < NITER; ++it) {
        if (it + 1 < NITER) {
            const int k0 = (it + 1) * GBK;
            const uint32_t base = sb + ((it + 1) & 1) * STGB;
            const uint32_t sA = base, sB = base + ABUF;
            #pragma unroll
            for (int i = 0; i < 4; i++) {
                int r = lr + i * 32;
                cp16(sA + (r * LDS_ + lc) * 4, A + (size_t)(m0 + r) * Cv + k0 + lc);
                cp16(sB + (r * LDS_ + lc) * 4, B + (size_t)(n0 + r) * Cv + k0 + lc);
            }
            asm volatile("cp.async.commit_group;");
            asm volatile("cp.async.wait_group 1;");
        } else {
            asm volatile("cp.async.wait_group 0;");
        }
        __syncthreads();

        const uint32_t base = sb + (it & 1) * STGB;
        const uint32_t sA = base, sB = base + ABUF;

        #pragma unroll
        for (int ks = 0; ks < 4; ++ks) {
            const int kk = ks * 8;
            uint32_t af[4][4], bf[4][2];
            #pragma unroll
            for (int mf = 0; mf < 4; ++mf) {
                int row = wm + mf * 16 + (lane & 15);
                int col = kk + ((lane >> 4) << 2);
                LDM_X4(af[mf][0], af[mf][1], af[mf][2], af[mf][3],
                       sA + (row * LDS_ + col) * 4);
            }
            #pragma unroll
            for (int np = 0; np < 2; ++np) {
                int row = wn + np * 16 + ((lane & 16) >> 1) + (lane & 7);
                int col = kk + ((lane & 8) >> 1);
                uint32_t r0, r1, r2, r3;
                LDM_X4(r0, r1, r2, r3, sB + (row * LDS_ + col) * 4);
                bf[np*2+0][0] = r0; bf[np*2+0][1] = r1;
                bf[np*2+1][0] = r2; bf[np*2+1][1] = r3;
            }
            #pragma unroll
            for (int mf = 0; mf < 4; ++mf)
                #pragma unroll
                for (int nf = 0; nf < 4; ++nf)
                    mma_tf32(acc[mf][nf], af[mf], bf[nf]);
        }
        __syncthreads();
    }

    float* C = C0; int nn = n0;
    if (C1 != nullptr && n0 >= 1024) {
        C = (n0 >= 2048) ? C2 : C1;
        nn = n0 & 1023;
    }

    const int rA = lane >> 2;
    const int cA = (lane & 3) * 2;
    #pragma unroll
    for (int mf = 0; mf < 4; ++mf)
        #pragma unroll
        for (int nf = 0; nf < 4; ++nf) {
            int row = m0 + wm + mf * 16 + rA;
            int col = nn + wn + nf * 8 + cA;
            float v0 = acc[mf][nf][0], v1 = acc[mf][nf][1];
            float v2 = acc[mf][nf][2], v3 = acc[mf][nf][3];
            if (rnd) { v0 = rnd_tf32(v0); v1 = rnd_tf32(v1);
                       v2 = rnd_tf32(v2); v3 = rnd_tf32(v3); }
            *(float2*)(C + (size_t)row * Cv + col)       = make_float2(v0, v1);
            *(float2*)(C + (size_t)(row + 8) * Cv + col) = make_float2(v2, v3);
        }
}

// ---------------------------------------------------------------------------
// Causal flash attention, mma.sync tf32, BM=256 (8 warps x 32 q-rows), BN=64.
// smem: Q[256][68] | K[2][64][68] | V[2][64][68] | Vt[64][68] | P[256][68]
//     = 226304 bytes. 1 CTA/SM.
// ---------------------------------------------------------------------------
#define FPAD 68
#define KVT  (64*FPAD)         // 4352 floats per K/V tile
#define QOFF 0
#define KOFF (256*FPAD)        // 17408
#define VOFF (KOFF + 2*KVT)    // 26112
#define TOFF (VOFF + 2*KVT)    // 34816  (Vt)
#define POFF (TOFF + KVT)      // 39168
#define FSMEM ((POFF + 256*FPAD) * 4)   // 226304 B

__global__ __launch_bounds__(256)
void flash_mma(const float* __restrict__ Qg, const float* __restrict__ Kg,
               const float* __restrict__ Vg, float* __restrict__ Og)
{
    extern __shared__ __align__(16) float fs[];
    const uint32_t sb  = smem_u32(fs);
    const uint32_t sQ  = sb + QOFF * 4;
    const uint32_t sK0 = sb + KOFF * 4;
    const uint32_t sV0 = sb + VOFF * 4;
    const uint32_t sVt = sb + TOFF * 4;
    const uint32_t sP  = sb + POFF * 4;
    float* Vt = fs + TOFF;

    const int tid = threadIdx.x;
    const int wid = tid >> 5, lane = tid & 31;
    const int g = lane >> 2, t = lane & 3;
    const int qt = (int)(gridDim.x - 1 - blockIdx.x);   // heavy CTAs first
    const int bh = blockIdx.y;
    const int b = bh >> 4, h = bh & 15;
    const int q0 = qt * 256;
    const int ktiles = 4 * qt + 4;
    const size_t base = (size_t)b * Tv * Cv + (size_t)h * Dv;

    // prologue: Q (256x64) + K/V tile 0 (64x64 each)
    {
        const float* qb = Qg + base + (size_t)q0 * Cv;
        const float* kb = Kg + base;
        const float* vb = Vg + base;
        #pragma unroll
        for (int i = 0; i < 16; i++) {
            int id = tid + i * 256, r = id >> 4, c = (id & 15) * 4;
            cp16(sQ + (r * FPAD + c) * 4, qb + (size_t)r * Cv + c);
        }
        #pragma unroll
        for (int i = 0; i < 4; i++) {
            int id = tid + i * 256, r = id >> 4, c = (id & 15) * 4;
            cp16(sK0 + (r * FPAD + c) * 4, kb + (size_t)r * Cv + c);
            cp16(sV0 + (r * FPAD + c) * 4, vb + (size_t)r * Cv + c);
        }
        asm volatile("cp.async.commit_group;");
    }

    float oacc[2][8][4];
    #pragma unroll
    for (int mf = 0; mf < 2; mf++)
        #pragma unroll
        for (int nf = 0; nf < 8; nf++)
            #pragma unroll
            for (int k = 0; k < 4; k++) oacc[mf][nf][k] = 0.f;
    float mrow[2][2], lrow[2][2];
    #pragma unroll
    for (int mf = 0; mf < 2; mf++) {
        mrow[mf][0] = -1e30f; mrow[mf][1] = -1e30f;
        lrow[mf][0] = 0.f;    lrow[mf][1] = 0.f;
    }
    uint32_t qf[2][8][4];

    for (int kt = 0; kt < ktiles; ++kt) {
        const int cur = kt & 1;
        asm volatile("cp.async.wait_group 0;");
        __syncthreads();
        if (kt + 1 < ktiles) {
            int nb = cur ^ 1;
            const float* kb = Kg + base + (size_t)((kt + 1) * 64) * Cv;
            const float* vb = Vg + base + (size_t)((kt + 1) * 64) * Cv;
            #pragma unroll
            for (int i = 0; i < 4; i++) {
                int id = tid + i * 256, r = id >> 4, c = (id & 15) * 4;
                cp16(sK0 + (nb * KVT + r * FPAD + c) * 4, kb + (size_t)r * Cv + c);
                cp16(sV0 + (nb * KVT + r * FPAD + c) * 4, vb + (size_t)r * Cv + c);
            }
            asm volatile("cp.async.commit_group;");
        }
        if (kt == 0) {   // preload Q frags, fold scale 2^-3 (tf32-exact)
            #pragma unroll
            for (int mf = 0; mf < 2; mf++)
                #pragma unroll
                for (int ks = 0; ks < 8; ks++) {
                    int row = wid * 32 + mf * 16 + (lane & 15);
                    int col = ks * 8 + ((lane >> 4) << 2);
                    LDM_X4(qf[mf][ks][0], qf[mf][ks][1], qf[mf][ks][2], qf[mf][ks][3],
                           sQ + (row * FPAD + col) * 4);
                    #pragma unroll
                    for (int i = 0; i < 4; i++)
                        qf[mf][ks][i] = __float_as_uint(__uint_as_float(qf[mf][ks][i]) * 0.125f);
                }
        }
        const uint32_t sKb = sK0 + cur * KVT * 4;
        const float*   Vn  = fs + VOFF + cur * KVT;

        // ---- transpose V(cur) -> Vt [d][j]
        {
            int j = tid >> 2, dbase = (tid & 3) * 16;
            #pragma unroll
            for (int i = 0; i < 4; i++) {
                float4 v = *(const float4*)&Vn[j * FPAD + dbase + i * 4];
                Vt[(dbase + i * 4 + 0) * FPAD + j] = v.x;
                Vt[(dbase + i * 4 + 1) * FPAD + j] = v.y;
                Vt[(dbase + i * 4 + 2) * FPAD + j] = v.z;
                Vt[(dbase + i * 4 + 3) * FPAD + j] = v.w;
            }
        }

        // ---- S = Q K^T
        float sacc[2][8][4];
        #pragma unroll
        for (int mf = 0; mf < 2; mf++)
            #pragma unroll
            for (int nf = 0; nf < 8; nf++)
                #pragma unroll
                for (int k = 0; k < 4; k++) sacc[mf][nf][k] = 0.f;

        #pragma unroll
        for (int ks = 0; ks < 8; ks++) {
            uint32_t bf[8][2];
            #pragma unroll
            for (int np = 0; np < 4; np++) {
                int row = np * 16 + ((lane & 16) >> 1) + (lane & 7);
                int col = ks * 8 + ((lane & 8) >> 1);
                uint32_t r0, r1, r2, r3;
                LDM_X4(r0, r1, r2, r3, sKb + (row * FPAD + col) * 4);
                bf[np*2+0][0] = r0; bf[np*2+0][1] = r1;
                bf[np*2+1][0] = r2; bf[np*2+1][1] = r3;
            }
            #pragma unroll
            for (int mf = 0; mf < 2; mf++)
                #pragma unroll
                for (int nf = 0; nf < 8; nf++)
                    mma_tf32(sacc[mf][nf], qf[mf][ks], bf[nf]);
        }

        // ---- causal mask (band tiles only)
        if (kt >= 4 * qt) {
            const int k0 = kt * 64;
            #pragma unroll
            for (int mf = 0; mf < 2; mf++) {
                int r0g = q0 + wid * 32 + mf * 16 + g, r1g = r0g + 8;
                #pragma unroll
                for (int nf = 0; nf < 8; nf++) {
                    int c0 = k0 + nf * 8 + 2 * t;
                    if (c0     > r0g) sacc[mf][nf][0] = -1e30f;
                    if (c0 + 1 > r0g) sacc[mf][nf][1] = -1e30f;
                    if (c0     > r1g) sacc[mf][nf][2] = -1e30f;
                    if (c0 + 1 > r1g) sacc[mf][nf][3] = -1e30f;
                }
            }
        }

        // ---- online softmax (quad reductions, rows g / g+8 per mf)
        #pragma unroll
        for (int mf = 0; mf < 2; mf++) {
            float mx0 = -1e30f, mx1 = -1e30f;
            #pragma unroll
            for (int nf = 0; nf < 8; nf++) {
                mx0 = fmaxf(mx0, fmaxf(sacc[mf][nf][0], sacc[mf][nf][1]));
                mx1 = fmaxf(mx1, fmaxf(sacc[mf][nf][2], sacc[mf][nf][3]));
            }
            #pragma unroll
            for (int off = 1; off < 4; off <<= 1) {
                mx0 = fmaxf(mx0, __shfl_xor_sync(0xffffffffu, mx0, off));
                mx1 = fmaxf(mx1, __shfl_xor_sync(0xffffffffu, mx1, off));
            }
            float nm0 = fmaxf(mrow[mf][0], mx0), nm1 = fmaxf(mrow[mf][1], mx1);
            float al0 = __expf(mrow[mf][0] - nm0), al1 = __expf(mrow[mf][1] - nm1);
            float rs0 = 0.f, rs1 = 0.f;
            #pragma unroll
            for (int nf = 0; nf < 8; nf++) {
                float p0 = rnd_tf32(__expf(sacc[mf][nf][0] - nm0));
                float p1 = rnd_tf32(__expf(sacc[mf][nf][1] - nm0));
                float p2 = rnd_tf32(__expf(sacc[mf][nf][2] - nm1));
                float p3 = rnd_tf32(__expf(sacc[mf][nf][3] - nm1));
                sacc[mf][nf][0] = p0; sacc[mf][nf][1] = p1;
                sacc[mf][nf][2] = p2; sacc[mf][nf][3] = p3;
                rs0 += p0 + p1; rs1 += p2 + p3;
            }
            #pragma unroll
            for (int off = 1; off < 4; off <<= 1) {
                rs0 += __shfl_xor_sync(0xffffffffu, rs0, off);
                rs1 += __shfl_xor_sync(0xffffffffu, rs1, off);
            }
            lrow[mf][0] = lrow[mf][0] * al0 + rs0; mrow[mf][0] = nm0;
            lrow[mf][1] = lrow[mf][1] * al1 + rs1; mrow[mf][1] = nm1;
            #pragma unroll
            for (int nf = 0; nf < 8; nf++) {
                oacc[mf][nf][0] *= al0; oacc[mf][nf][1] *= al0;
                oacc[mf][nf][2] *= al1; oacc[mf][nf][3] *= al1;
            }
        }

        // ---- P -> smem (warp-private rows)
        {
            float* Pw = fs + POFF;
            #pragma unroll
            for (int mf = 0; mf < 2; mf++) {
                int pr0 = wid * 32 + mf * 16 + g, pr1 = pr0 + 8;
                #pragma unroll
                for (int nf = 0; nf < 8; nf++) {
                    *(float2*)&Pw[pr0 * FPAD + nf * 8 + 2 * t] =
                        make_float2(sacc[mf][nf][0], sacc[mf][nf][1]);
                    *(float2*)&Pw[pr1 * FPAD + nf * 8 + 2 * t] =
                        make_float2(sacc[mf][nf][2], sacc[mf][nf][3]);
                }
            }
        }
        // Vt complete (all threads) + own P rows written
        __syncthreads();

        // ---- O += P V  (A = P, B = Vt, both via ldmatrix)
        #pragma unroll
        for (int ks = 0; ks < 8; ks++) {
            uint32_t af[2][4];
            #pragma unroll
            for (int mf = 0; mf < 2; mf++) {
                int row = wid * 32 + mf * 16 + (lane & 15);
                int col = ks * 8 + ((lane >> 4) << 2);
                LDM_X4(af[mf][0], af[mf][1], af[mf][2], af[mf][3],
                       sP + (row * FPAD + col) * 4);
            }
            uint32_t bf[8][2];
            #pragma unroll
            for (int np = 0; np < 4; np++) {
                int brow = np * 16 + ((lane & 16) >> 1) + (lane & 7);
                int bcol = ks * 8 + ((lane & 8) >> 1);
                uint32_t r0, r1, r2, r3;
                LDM_X4(r0, r1, r2, r3, sVt + (brow * FPAD + bcol) * 4);
                bf[np*2+0][0] = r0; bf[np*2+0][1] = r1;
                bf[np*2+1][0] = r2; bf[np*2+1][1] = r3;
            }
            #pragma unroll
            for (int mf = 0; mf < 2; mf++)
                #pragma unroll
                for (int nf = 0; nf < 8; nf++)
                    mma_tf32(oacc[mf][nf], af[mf], bf[nf]);
        }
    }

    // ---- epilogue
    #pragma unroll
    for (int mf = 0; mf < 2; mf++) {
        float inv0 = 1.f / lrow[mf][0], inv1 = 1.f / lrow[mf][1];
        int r0g = q0 + wid * 32 + mf * 16 + g, r1g = r0g + 8;
        #pragma unroll
        for (int nf = 0; nf < 8; nf++) {
            int c = nf * 8 + 2 * t;
            *(float2*)(Og + base + (size_t)r0g * Cv + c) =
                make_float2(rnd_tf32(oacc[mf][nf][0] * inv0), rnd_tf32(oacc[mf][nf][1] * inv0));
            *(float2*)(Og + base + (size_t)r1g * Cv + c) =
                make_float2(rnd_tf32(oacc[mf][nf][2] * inv1), rnd_tf32(oacc[mf][nf][3] * inv1));
        }
    }
}

// ---------------------------------------------------------------------------
extern "C" void kernel_launch(void* const* d_in, const int* in_sizes, int n_in,
                              void* d_out, int out_size)
{
    const float* x  = (const float*)d_in[0];
    const float* wq = (const float*)d_in[1];
    const float* wk = (const float*)d_in[2];
    const float* wv = (const float*)d_in[3];
    const float* wo = (const float*)d_in[4];
    float* out = (float*)d_out;

    float *qp, *kp, *vp, *ap, *xr, *wr;
    cudaGetSymbolAddress((void**)&qp, g_q);
    cudaGetSymbolAddress((void**)&kp, g_k);
    cudaGetSymbolAddress((void**)&vp, g_v);
    cudaGetSymbolAddress((void**)&ap, g_att);
    cudaGetSymbolAddress((void**)&xr, g_xr);
    cudaGetSymbolAddress((void**)&wr, g_wr);

    round_tf32_k<<<(Mv*Cv/4 + 255)/256, 256>>>((const float4*)x, (float4*)xr, Mv*Cv/4);
    round_tf32_w4<<<(4*Cv*Cv/4 + 255)/256, 256>>>((const float4*)wq, (const float4*)wk,
                                                  (const float4*)wv, (const float4*)wo,
                                                  (float4*)wr);

    const int gsmem = 2 * STGB;
    cudaFuncSetAttribute(gemm_tf32, cudaFuncAttributeMaxDynamicSharedMemorySize, gsmem);

    // fused QKV: B = [wq; wk; wv] (3072 x 1024), outputs split per n-block
    gemm_tf32<<<dim3(24, 64), 256, gsmem>>>(xr, wr, qp, kp, vp, 1);

    cudaFuncSetAttribute(flash_mma, cudaFuncAttributeMaxDynamicSharedMemorySize, FSMEM);
    flash_mma<<<dim3(Tv/256, Bv*Hv), 256, FSMEM>>>(qp, kp, vp, ap);

    gemm_tf32<<<dim3(8, 64), 256, gsmem>>>(ap, wr + 3*(size_t)Cv*Cv, out,
                                           nullptr, nullptr, 0);
}